// round 1
// baseline (speedup 1.0000x reference)
#include <cuda_runtime.h>
#include <math.h>

// ---------------- problem constants ----------------
#define BATCH   64
#define RESO    28
#define NTOK    784            // 28*28
#define DIMC    384
#define CBR     192            // per-branch channels
#define HEADS   8
#define CHH     24             // CBR / HEADS
#define WIN     196            // window tokens
#define GPB     32             // windows*heads per batch per branch
#define HID     1536
#define MTOK    (BATCH*NTOK)   // 50176
#define MGEN    (BATCH*GPB)    // 2048
#define KGEN    392            // WIN*DMIX
#define NGEN    38416          // WIN*WIN

// ---------------- scratch (static device allocations) ----------------
__device__ __align__(16) float g_an[(size_t)MTOK*DIMC];
__device__ __align__(16) float g_wv0[(size_t)MGEN*KGEN];
__device__ __align__(16) float g_wv1[(size_t)MGEN*KGEN];
__device__ __align__(16) float g_logits[(size_t)MGEN*NGEN];
__device__ __align__(16) float g_attn[(size_t)MTOK*DIMC];
__device__ __align__(16) float g_xmid[(size_t)MTOK*DIMC];
__device__ __align__(16) float g_mn[(size_t)MTOK*DIMC];
__device__ __align__(16) float g_h[(size_t)MTOK*HID];

// ---------------- center norm: w*(scale*(x-mean)) + b ----------------
__global__ void knorm(const float* __restrict__ x, const float* __restrict__ w,
                      const float* __restrict__ bb, float* __restrict__ out) {
    int t = blockIdx.x;
    const float* xr = x + (size_t)t * DIMC;
    float* orow = out + (size_t)t * DIMC;
    int tid = threadIdx.x; // 128
    float v0 = xr[tid], v1 = xr[tid + 128], v2 = xr[tid + 256];
    float s = v0 + v1 + v2;
#pragma unroll
    for (int o = 16; o > 0; o >>= 1) s += __shfl_xor_sync(0xffffffffu, s, o);
    __shared__ float red[4];
    if ((tid & 31) == 0) red[tid >> 5] = s;
    __syncthreads();
    float u = (red[0] + red[1] + red[2] + red[3]) * (1.0f / DIMC);
    const float sc = (float)DIMC / (float)(DIMC - 1);
    orow[tid]       = w[tid]       * (sc * (v0 - u)) + bb[tid];
    orow[tid + 128] = w[tid + 128] * (sc * (v1 - u)) + bb[tid + 128];
    orow[tid + 256] = w[tid + 256] * (sc * (v2 - u)) + bb[tid + 256];
}

// ---------------- compress + window rearrange for both branches ----------------
// wv[b*GPB+g][s*2+di] = dot(an[b,n,branch*192 : +192], cw[:, head*2+di]) + cb
__global__ void kcompress(const float* __restrict__ an,
                          const float* __restrict__ c0w, const float* __restrict__ c0b,
                          const float* __restrict__ c1w, const float* __restrict__ c1b,
                          float* __restrict__ wv0, float* __restrict__ wv1) {
    int tok = blockIdx.x;           // b*NTOK + n
    int b = tok / NTOK, n = tok % NTOK;
    __shared__ float xs[DIMC];
    for (int i = threadIdx.x; i < DIMC; i += 32)
        xs[i] = an[(size_t)tok * DIMC + i];
    __syncwarp();
    int tid = threadIdx.x;          // 32 threads
    int branch = tid >> 4;
    int j = tid & 15;               // head*2 + di
    const float* cw  = branch ? c1w : c0w;
    const float* cbv = branch ? c1b : c0b;
    const float* xb = xs + branch * CBR;
    float acc = cbv[j];
#pragma unroll 4
    for (int k = 0; k < CBR; k++) acc = fmaf(xb[k], cw[k * 16 + j], acc);
    int head = j >> 1, di = j & 1;
    int row = n / RESO, col = n % RESO;
    int g, s;
    if (branch == 0) { // H_sp=28, W_sp=7, n1=1, n2=4
        int n2i = col / 7; int h = row; int w = col % 7;
        g = n2i * HEADS + head; s = h * 7 + w;
    } else {           // H_sp=7, W_sp=28, n1=4, n2=1
        int n1i = row / 7; int h = row % 7;
        g = n1i * HEADS + head; s = h * 28 + col;
    }
    float* dst = branch ? wv1 : wv0;
    dst[(size_t)(b * GPB + g) * KGEN + s * 2 + di] = acc;
}

// ---------------- generic tiled SGEMM with fused epilogue ----------------
// C = epi(A(MxK) @ B(KxN) + bias)
// EPI 0: none; 1: exact GELU; 2: out = res + alpha[n]*val
template <int EPI>
__global__ __launch_bounds__(256) void sgemm(
    const float* __restrict__ A, const float* __restrict__ Bm,
    const float* __restrict__ bias, const float* __restrict__ res,
    const float* __restrict__ alpha, float* __restrict__ C,
    int M, int N, int K) {
    __shared__ float As[8][128];
    __shared__ float Bs[8][128];
    int tid = threadIdx.x;
    int row0 = blockIdx.y * 128, col0 = blockIdx.x * 128;
    int tx = tid & 15, ty = tid >> 4;

    int aRow = tid >> 1;
    int aCol = (tid & 1) * 4;
    int bRow = tid >> 5;
    int bCol = (tid & 31) * 4;

    bool aValid = (row0 + aRow) < M;
    bool bValid = (col0 + bCol) < N;   // N % 4 == 0 for all our shapes

    const float* aPtr = A + (size_t)(row0 + aRow) * K + aCol;
    const float* bPtr = Bm + (size_t)bRow * N + col0 + bCol;

    float acc[8][8] = {};
    for (int k0 = 0; k0 < K; k0 += 8) {
        float4 av = aValid ? *(const float4*)aPtr : make_float4(0, 0, 0, 0);
        float4 bv = bValid ? *(const float4*)bPtr : make_float4(0, 0, 0, 0);
        As[aCol + 0][aRow] = av.x; As[aCol + 1][aRow] = av.y;
        As[aCol + 2][aRow] = av.z; As[aCol + 3][aRow] = av.w;
        *(float4*)&Bs[bRow][bCol] = bv;
        __syncthreads();
#pragma unroll
        for (int kk = 0; kk < 8; kk++) {
            float4 a0 = *(const float4*)&As[kk][ty * 8];
            float4 a1 = *(const float4*)&As[kk][ty * 8 + 4];
            float4 b0 = *(const float4*)&Bs[kk][tx * 8];
            float4 b1 = *(const float4*)&Bs[kk][tx * 8 + 4];
            float ar[8] = {a0.x, a0.y, a0.z, a0.w, a1.x, a1.y, a1.z, a1.w};
            float br[8] = {b0.x, b0.y, b0.z, b0.w, b1.x, b1.y, b1.z, b1.w};
#pragma unroll
            for (int i = 0; i < 8; i++)
#pragma unroll
                for (int j = 0; j < 8; j++)
                    acc[i][j] = fmaf(ar[i], br[j], acc[i][j]);
        }
        __syncthreads();
        aPtr += 8;
        bPtr += (size_t)8 * N;
    }
#pragma unroll
    for (int i = 0; i < 8; i++) {
        int r = row0 + ty * 8 + i;
        if (r >= M) continue;
#pragma unroll
        for (int j = 0; j < 8; j++) {
            int c = col0 + tx * 8 + j;
            if (c >= N) continue;
            float v = acc[i][j] + bias[c];
            size_t idx = (size_t)r * N + c;
            if (EPI == 1) v = 0.5f * v * (1.0f + erff(v * 0.70710678118654752f));
            if (EPI == 2) v = res[idx] + alpha[c] * v;
            C[idx] = v;
        }
    }
}

// ---------------- fused softmax(source axis) + V@W + scatter ----------------
// one block per (b, g). logits row (196s x 196t) lives in SMEM.
__global__ __launch_bounds__(256) void kmix(const float* __restrict__ logits,
                                            const float* __restrict__ an,
                                            float* __restrict__ attn, int branch) {
    extern __shared__ float sm[];
    float* p    = sm;                    // 38416 logits -> probabilities*sum
    float* v    = sm + NGEN;             // 24 x 196 values
    float* sInv = sm + NGEN + CHH * WIN; // 196 inverse sums

    int bg = blockIdx.x;
    int b = bg / GPB, g = bg % GPB;
    int head = g % HEADS, wi = g / HEADS; // wi = n2_i (br0) or n1_i (br1)
    int coff = branch * CBR + head * CHH;

    const float4* lrow = (const float4*)(logits + (size_t)bg * NGEN);
    float4* p4 = (float4*)p;
    for (int i = threadIdx.x; i < NGEN / 4; i += blockDim.x) p4[i] = lrow[i];

    for (int i = threadIdx.x; i < CHH * WIN; i += blockDim.x) {
        int ch = i / WIN, s = i % WIN;
        int n;
        if (branch == 0) { int h = s / 7, w = s % 7; n = h * RESO + wi * 7 + w; }
        else             { int h = s / 28, w = s % 28; n = (wi * 7 + h) * RESO + w; }
        v[i] = an[((size_t)b * NTOK + n) * DIMC + coff + ch];
    }
    __syncthreads();

    int t = threadIdx.x;
    if (t < WIN) {
        float mx = -1e30f;
        for (int s = 0; s < WIN; s++) mx = fmaxf(mx, p[s * WIN + t]);
        float sum = 0.0f;
        for (int s = 0; s < WIN; s++) {
            float e = __expf(p[s * WIN + t] - mx);
            p[s * WIN + t] = e;
            sum += e;
        }
        sInv[t] = 1.0f / sum;
    }
    __syncthreads();

    for (int o = threadIdx.x; o < CHH * WIN; o += blockDim.x) {
        int ch = o / WIN, tt = o % WIN;
        float acc = 0.0f;
        const float* vr = v + ch * WIN;
#pragma unroll 4
        for (int s = 0; s < WIN; s++) acc = fmaf(vr[s], p[s * WIN + tt], acc);
        acc *= sInv[tt];
        int n;
        if (branch == 0) { int h = tt / 7, w = tt % 7; n = h * RESO + wi * 7 + w; }
        else             { int h = tt / 28, w = tt % 28; n = (wi * 7 + h) * RESO + w; }
        attn[((size_t)b * NTOK + n) * DIMC + coff + ch] = acc;
    }
}

// ---------------- launch ----------------
extern "C" void kernel_launch(void* const* d_in, const int* in_sizes, int n_in,
                              void* d_out, int out_size) {
    const float* x   = (const float*)d_in[0];
    const float* n1w = (const float*)d_in[1];
    const float* n1b = (const float*)d_in[2];
    const float* n2w = (const float*)d_in[3];
    const float* n2b = (const float*)d_in[4];
    const float* c0w = (const float*)d_in[5];
    const float* c0b = (const float*)d_in[6];
    const float* g0w = (const float*)d_in[7];
    const float* g0b = (const float*)d_in[8];
    const float* c1w = (const float*)d_in[9];
    const float* c1b = (const float*)d_in[10];
    const float* g1w = (const float*)d_in[11];
    const float* g1b = (const float*)d_in[12];
    const float* pw  = (const float*)d_in[13];
    const float* pb  = (const float*)d_in[14];
    const float* f1w = (const float*)d_in[15];
    const float* f1b = (const float*)d_in[16];
    const float* f2w = (const float*)d_in[17];
    const float* f2b = (const float*)d_in[18];
    const float* a1  = (const float*)d_in[19];
    const float* a2  = (const float*)d_in[20];
    float* out = (float*)d_out;

    float *an, *wv0, *wv1, *logits, *attn, *xmid, *mn, *h;
    cudaGetSymbolAddress((void**)&an, g_an);
    cudaGetSymbolAddress((void**)&wv0, g_wv0);
    cudaGetSymbolAddress((void**)&wv1, g_wv1);
    cudaGetSymbolAddress((void**)&logits, g_logits);
    cudaGetSymbolAddress((void**)&attn, g_attn);
    cudaGetSymbolAddress((void**)&xmid, g_xmid);
    cudaGetSymbolAddress((void**)&mn, g_mn);
    cudaGetSymbolAddress((void**)&h, g_h);

    int smix = (NGEN + CHH * WIN + WIN) * sizeof(float); // 173264 B
    cudaFuncSetAttribute(kmix, cudaFuncAttributeMaxDynamicSharedMemorySize, smix);

    // 1. norm1
    knorm<<<MTOK, 128>>>(x, n1w, n1b, an);
    // 2. compress both branches
    kcompress<<<MTOK, 32>>>(an, c0w, c0b, c1w, c1b, wv0, wv1);
    // 3/4. branch 0: logits GEMM + fused softmax/AV/scatter
    dim3 gl((NGEN + 127) / 128, MGEN / 128);
    sgemm<0><<<gl, 256>>>(wv0, g0w, g0b, nullptr, nullptr, logits, MGEN, NGEN, KGEN);
    kmix<<<MGEN, 256, smix>>>(logits, an, attn, 0);
    // 5/6. branch 1 (reuses logits buffer)
    sgemm<0><<<gl, 256>>>(wv1, g1w, g1b, nullptr, nullptr, logits, MGEN, NGEN, KGEN);
    kmix<<<MGEN, 256, smix>>>(logits, an, attn, 1);
    // 7. proj + alpha1 residual
    dim3 gp(DIMC / 128, MTOK / 128);
    sgemm<2><<<gp, 256>>>(attn, pw, pb, x, a1, xmid, MTOK, DIMC, DIMC);
    // 8. norm2
    knorm<<<MTOK, 128>>>(xmid, n2w, n2b, mn);
    // 9. fc1 + GELU
    dim3 gf1(HID / 128, MTOK / 128);
    sgemm<1><<<gf1, 256>>>(mn, f1w, f1b, nullptr, nullptr, h, MTOK, HID, DIMC);
    // 10. fc2 + alpha2 residual -> output
    sgemm<2><<<gp, 256>>>(h, f2w, f2b, xmid, a2, out, MTOK, DIMC, HID);
}